// round 1
// baseline (speedup 1.0000x reference)
#include <cuda_runtime.h>
#include <cstdint>

// ---------------------------------------------------------------------------
// SpikeMLP: out = LIF(x @ w1^T) @ w2^T, rate = mean(spikes)
//   x  : (16,4,256,512)  f32   -> rows M1 = 16*4*256 = 16384, K1 = 512
//   w1 : (2048,512)      f32   -> N1 = 2048 (K-major, NT gemm)
//   w2 : (512,2048)      f32   -> N2 = 512  (K-major, NT gemm)
// LIF over t=4 with beta = 1 - 1/20, threshold 1.0, hard reset.
// ---------------------------------------------------------------------------

#define M1 16384
#define N1 2048
#define K1 512
#define N2 512
#define K2 2048

#define TOTAL_H (16384UL * 2048UL)      // 33,554,432
#define LIF_THREADS (16 * 256 * 2048)   // 8,388,608  (b,s,hid)
#define LIF_BLOCKS (LIF_THREADS / 256)  // 32768

// Scratch (device globals: no allocation allowed in kernel_launch)
__device__ float g_h[TOTAL_H];     // fc1 output (membrane inputs)
__device__ float g_spk[TOTAL_H];   // spikes as 0.0/1.0 f32
__device__ unsigned int g_partial[LIF_BLOCKS];

// ---------------------------------------------------------------------------
// fp32 NT SGEMM: C[m,n] = sum_k A[m*K+k] * B[n*K+k]
// BM=BN=128, BK=8, 16x16 threads, 8x8 micro-tile.
// Requires M%128==0, N%128==0, K%8==0 (true for both GEMMs here).
// ---------------------------------------------------------------------------
__global__ __launch_bounds__(256, 2) void sgemm_nt(
    const float* __restrict__ A, const float* __restrict__ B,
    float* __restrict__ C, int M, int N, int K)
{
    __shared__ float As[8][128];
    __shared__ float Bs[8][128];

    const int tid = threadIdx.x;
    const int tx  = tid & 15;        // col group
    const int ty  = tid >> 4;        // row group
    const int m0  = blockIdx.y * 128;
    const int n0  = blockIdx.x * 128;

    const float* Ab = A + (size_t)m0 * K;
    const float* Bb = B + (size_t)n0 * K;

    const int lrow = tid >> 1;        // 0..127
    const int lcol = (tid & 1) * 4;   // 0 or 4

    float acc[8][8];
    #pragma unroll
    for (int i = 0; i < 8; i++)
        #pragma unroll
        for (int j = 0; j < 8; j++) acc[i][j] = 0.0f;

    for (int k0 = 0; k0 < K; k0 += 8) {
        float4 av = *(const float4*)(Ab + (size_t)lrow * K + k0 + lcol);
        float4 bv = *(const float4*)(Bb + (size_t)lrow * K + k0 + lcol);
        As[lcol + 0][lrow] = av.x; As[lcol + 1][lrow] = av.y;
        As[lcol + 2][lrow] = av.z; As[lcol + 3][lrow] = av.w;
        Bs[lcol + 0][lrow] = bv.x; Bs[lcol + 1][lrow] = bv.y;
        Bs[lcol + 2][lrow] = bv.z; Bs[lcol + 3][lrow] = bv.w;
        __syncthreads();

        #pragma unroll
        for (int k = 0; k < 8; k++) {
            float a[8], b[8];
            #pragma unroll
            for (int i = 0; i < 4; i++) {
                float4 t4 = *(const float4*)&As[k][ty * 8 + i * 4 - (i/1)*0];
                (void)t4; // (kept simple below)
            }
            #pragma unroll
            for (int i = 0; i < 8; i++) a[i] = As[k][ty * 8 + i];
            #pragma unroll
            for (int j = 0; j < 8; j++) b[j] = Bs[k][tx * 8 + j];
            #pragma unroll
            for (int i = 0; i < 8; i++)
                #pragma unroll
                for (int j = 0; j < 8; j++)
                    acc[i][j] = fmaf(a[i], b[j], acc[i][j]);
        }
        __syncthreads();
    }

    #pragma unroll
    for (int i = 0; i < 8; i++) {
        float* Crow = C + (size_t)(m0 + ty * 8 + i) * N + n0 + tx * 8;
        *(float4*)(Crow + 0) = make_float4(acc[i][0], acc[i][1], acc[i][2], acc[i][3]);
        *(float4*)(Crow + 4) = make_float4(acc[i][4], acc[i][5], acc[i][6], acc[i][7]);
    }
}

// ---------------------------------------------------------------------------
// LIF scan over t=4. One thread per (b, s, hid). h layout: (b, t, s, hid).
// v = beta*v + h; spk = (v > 1); v = spk ? 0 : v.
// Per-block spike counts -> g_partial (fully overwritten each launch).
// ---------------------------------------------------------------------------
__global__ __launch_bounds__(256) void lif_kernel()
{
    const size_t idx = (size_t)blockIdx.x * 256 + threadIdx.x; // (b,s,hid)
    const int    hid = (int)(idx & 2047);
    const size_t bs  = idx >> 11;          // b*256 + s
    const size_t b   = bs >> 8;
    const size_t s   = bs & 255;
    const size_t base    = ((b * 4) * 256 + s) * 2048 + hid;
    const size_t tstride = 256UL * 2048UL;

    const float beta = (float)(1.0 - 1.0 / 20.0);
    float v = 0.0f;
    int cnt = 0;

    #pragma unroll
    for (int t = 0; t < 4; t++) {
        v = fmaf(beta, v, g_h[base + (size_t)t * tstride]);
        bool fire = (v > 1.0f);
        g_spk[base + (size_t)t * tstride] = fire ? 1.0f : 0.0f;
        cnt += fire ? 1 : 0;
        v = fire ? 0.0f : v;
    }

    // block reduce spike count
    #pragma unroll
    for (int o = 16; o; o >>= 1) cnt += __shfl_down_sync(0xFFFFFFFFu, cnt, o);
    __shared__ int warpsum[8];
    if ((threadIdx.x & 31) == 0) warpsum[threadIdx.x >> 5] = cnt;
    __syncthreads();
    if (threadIdx.x == 0) {
        int tot = 0;
        #pragma unroll
        for (int w = 0; w < 8; w++) tot += warpsum[w];
        g_partial[blockIdx.x] = (unsigned int)tot;
    }
}

// ---------------------------------------------------------------------------
// rate = total_spikes / 33554432 -> out[out_size-1]
// ---------------------------------------------------------------------------
__global__ __launch_bounds__(1024) void rate_kernel(float* __restrict__ out_rate)
{
    unsigned long long s = 0;
    for (int i = threadIdx.x; i < LIF_BLOCKS; i += 1024) s += g_partial[i];
    #pragma unroll
    for (int o = 16; o; o >>= 1) s += __shfl_down_sync(0xFFFFFFFFu, s, o);
    __shared__ unsigned long long sh[32];
    if ((threadIdx.x & 31) == 0) sh[threadIdx.x >> 5] = s;
    __syncthreads();
    if (threadIdx.x == 0) {
        unsigned long long tot = 0;
        #pragma unroll
        for (int w = 0; w < 32; w++) tot += sh[w];
        *out_rate = (float)((double)tot / 33554432.0);
    }
}

// ---------------------------------------------------------------------------
extern "C" void kernel_launch(void* const* d_in, const int* in_sizes, int n_in,
                              void* d_out, int out_size)
{
    const float* x  = (const float*)d_in[0];
    const float* w1 = (const float*)d_in[1];
    const float* w2 = (const float*)d_in[2];
    float* out = (float*)d_out;

    float* h;   cudaGetSymbolAddress((void**)&h,   g_h);
    float* spk; cudaGetSymbolAddress((void**)&spk, g_spk);

    // GEMM1: h = x @ w1^T   (M=16384, N=2048, K=512)
    sgemm_nt<<<dim3(N1 / 128, M1 / 128), 256>>>(x, w1, h, M1, N1, K1);

    // LIF scan + spike counting
    lif_kernel<<<LIF_BLOCKS, 256>>>();

    // rate -> last output element
    rate_kernel<<<1, 1024>>>(out + (out_size - 1));

    // GEMM2: out = spk @ w2^T (M=16384, N=512, K=2048)
    sgemm_nt<<<dim3(N2 / 128, M1 / 128), 256>>>(spk, w2, out, M1, N2, K2);
}

// round 4
// speedup vs baseline: 1.5905x; 1.5905x over previous
#include <cuda_runtime.h>
#include <cuda_fp16.h>
#include <cstdint>

// ============================================================================
// SpikeMLP via mma.sync.m16n8k16 fp16 tensor cores + sparse fp32 fixup.
//   GEMM1: h = x @ w1^T  -- fp16x2 split both operands (4 products, K'=2048)
//   LIF scan (t=4): provisional spikes; neurons with |v-1| < EPS are flagged
//   FIXUP: flagged neurons recomputed exactly in fp32 (sequential fma, same
//          arithmetic as the R1 fp32 kernel that matched the reference)
//   GEMM2: out = spk @ w2^T -- fp16x2 split on w2 (2 products, K'=4096)
// ============================================================================

#define STAGES 4
#define BM 128
#define BN 128
#define BK 64
#define STAGE_BYTES (BM * BK * 2)               // 16 KB
#define SMEM_B_OFF  (STAGES * STAGE_BYTES)      // 64 KB
#define SMEM_ALLOC  (2 * STAGES * STAGE_BYTES + 256)

#define FLAG_EPS 2e-3f
#define FLAG_CAP (1u << 22)

// ---------------- device scratch (no allocation allowed) -------------------
__device__ __align__(256) __half g_xsplit[16384UL * 1024UL];   // 32 MB
__device__ __align__(256) __half g_w1split[2048UL * 1024UL];   //  4 MB
__device__ __align__(256) __half g_w2split[512UL * 4096UL];    //  4 MB
__device__ __align__(256) float  g_h[16384UL * 2048UL];        // 128 MB
__device__ __align__(256) __half g_spk[16384UL * 2048UL];      //  64 MB
__device__ unsigned int g_partial[32768];
__device__ unsigned int g_flags[FLAG_CAP];                      // 16 MB
__device__ unsigned int g_flag_count;
__device__ int          g_fix_delta;

struct KMap { int a[4]; int b[4]; };

// ---------------- PTX helpers ----------------------------------------------
__device__ __forceinline__ uint32_t smem_u32(const void* p) {
    uint32_t a;
    asm("{ .reg .u64 t; cvta.to.shared.u64 t, %1; cvt.u32.u64 %0, t; }"
        : "=r"(a) : "l"(p));
    return a;
}
__device__ __forceinline__ void cp16(uint32_t dst, const void* src) {
    asm volatile("cp.async.cg.shared.global [%0], [%1], 16;\n"
                 :: "r"(dst), "l"(src));
}
__device__ __forceinline__ void ldsm_x4(uint32_t r[4], uint32_t addr) {
    asm volatile("ldmatrix.sync.aligned.m8n8.x4.shared.b16 {%0,%1,%2,%3}, [%4];\n"
                 : "=r"(r[0]), "=r"(r[1]), "=r"(r[2]), "=r"(r[3]) : "r"(addr));
}
__device__ __forceinline__ void mma16816(float c[4], const uint32_t a[4],
                                         const uint32_t* b) {
    asm volatile(
        "mma.sync.aligned.m16n8k16.row.col.f32.f16.f16.f32 "
        "{%0,%1,%2,%3}, {%4,%5,%6,%7}, {%8,%9}, {%0,%1,%2,%3};\n"
        : "+f"(c[0]), "+f"(c[1]), "+f"(c[2]), "+f"(c[3])
        : "r"(a[0]), "r"(a[1]), "r"(a[2]), "r"(a[3]), "r"(b[0]), "r"(b[1]));
}

// ============================================================================
// Generic fp16 NT GEMM (tensor cores) with K-block indirection:
//   C[m,n] = out_scale * sum_k A[m, amap(k)] * B[n, bmap(k)]
// ============================================================================
__global__ __launch_bounds__(256, 1) void gemm_f16(
    const __half* __restrict__ A, const __half* __restrict__ B,
    float* __restrict__ C, int ldc, int nchunks,
    int a_rs, int b_rs, int kb_log2, float out_scale, KMap map)
{
    extern __shared__ uint8_t dynsmem[];
    const uint32_t base = (smem_u32(dynsmem) + 127u) & ~127u;

    const int tid  = threadIdx.x;
    const int wid  = tid >> 5;
    const int lane = tid & 31;
    const int m0   = blockIdx.y * BM;
    const int n0   = blockIdx.x * BN;
    const int warp_m = (wid >> 2) * 64;   // 2 warps along M
    const int warp_n = (wid & 3) * 32;    // 4 warps along N

    int a_rb[4], a_xr[4];
    #pragma unroll
    for (int mt = 0; mt < 4; mt++) {
        const int r = warp_m + mt * 16 + (lane & 15);
        a_rb[mt] = r * 128;
        a_xr[mt] = (r & 7) << 4;
    }
    const int a_c0 = (lane >> 4) * 16;
    int b_rb[2], b_xr[2];
    {
        const int rl = (lane & 7) + ((lane >> 4) << 3);
        #pragma unroll
        for (int p = 0; p < 2; p++) {
            const int r = warp_n + p * 16 + rl;
            b_rb[p] = r * 128;
            b_xr[p] = (r & 7) << 4;
        }
    }
    const int b_c0 = ((lane >> 3) & 1) * 16;

    const int kbm = (1 << kb_log2) - 1;

    auto load_chunk = [&](int chunk, int slot) {
        const int k0 = chunk * BK;
        const int kb = k0 >> kb_log2;
        const size_t a_off = ((size_t)map.a[kb] << kb_log2) + (k0 & kbm);
        const size_t b_off = ((size_t)map.b[kb] << kb_log2) + (k0 & kbm);
        const uint32_t sA = base + slot * STAGE_BYTES;
        const uint32_t sB = base + SMEM_B_OFF + slot * STAGE_BYTES;
        #pragma unroll
        for (int r = 0; r < 4; r++) {
            const int idx = tid + r * 256;
            const int row = idx >> 3;
            const int cb  = (idx & 7) * 16;
            cp16(sA + row * 128 + (cb ^ ((row & 7) << 4)),
                 A + (size_t)(m0 + row) * a_rs + a_off + (cb >> 1));
            cp16(sB + row * 128 + (cb ^ ((row & 7) << 4)),
                 B + (size_t)(n0 + row) * b_rs + b_off + (cb >> 1));
        }
    };

    float acc[4][4][4];
    #pragma unroll
    for (int mt = 0; mt < 4; mt++)
        #pragma unroll
        for (int nt = 0; nt < 4; nt++)
            #pragma unroll
            for (int q = 0; q < 4; q++) acc[mt][nt][q] = 0.0f;

    #pragma unroll
    for (int j = 0; j < STAGES - 1; j++) {
        load_chunk(j, j);
        asm volatile("cp.async.commit_group;\n" ::: "memory");
    }

    for (int i = 0; i < nchunks; i++) {
        asm volatile("cp.async.wait_group %0;\n" :: "n"(STAGES - 2));
        __syncthreads();
        const int lc = i + STAGES - 1;
        if (lc < nchunks) load_chunk(lc, lc & (STAGES - 1));
        asm volatile("cp.async.commit_group;\n" ::: "memory");

        const uint32_t sA = base + (i & (STAGES - 1)) * STAGE_BYTES;
        const uint32_t sB = base + SMEM_B_OFF + (i & (STAGES - 1)) * STAGE_BYTES;

        uint32_t af[2][4][4], bf[2][2][4];
        #pragma unroll
        for (int mt = 0; mt < 4; mt++)
            ldsm_x4(af[0][mt], sA + a_rb[mt] + ((a_c0) ^ a_xr[mt]));
        #pragma unroll
        for (int p = 0; p < 2; p++)
            ldsm_x4(bf[0][p], sB + b_rb[p] + ((b_c0) ^ b_xr[p]));

        #pragma unroll
        for (int ks = 0; ks < 4; ks++) {
            const int cur = ks & 1, nxt = cur ^ 1;
            if (ks < 3) {
                const int c = (ks + 1) * 32;
                #pragma unroll
                for (int mt = 0; mt < 4; mt++)
                    ldsm_x4(af[nxt][mt], sA + a_rb[mt] + ((c + a_c0) ^ a_xr[mt]));
                #pragma unroll
                for (int p = 0; p < 2; p++)
                    ldsm_x4(bf[nxt][p], sB + b_rb[p] + ((c + b_c0) ^ b_xr[p]));
            }
            #pragma unroll
            for (int mt = 0; mt < 4; mt++)
                #pragma unroll
                for (int nt = 0; nt < 4; nt++)
                    mma16816(acc[mt][nt], af[cur][mt],
                             &bf[cur][nt >> 1][(nt & 1) * 2]);
        }
    }

    #pragma unroll
    for (int mt = 0; mt < 4; mt++) {
        #pragma unroll
        for (int nt = 0; nt < 4; nt++) {
            const int row = m0 + warp_m + mt * 16 + (lane >> 2);
            const int col = n0 + warp_n + nt * 8 + (lane & 3) * 2;
            float* c0 = C + (size_t)row * ldc + col;
            float* c1 = C + (size_t)(row + 8) * ldc + col;
            *(float2*)c0 = make_float2(acc[mt][nt][0] * out_scale,
                                       acc[mt][nt][1] * out_scale);
            *(float2*)c1 = make_float2(acc[mt][nt][2] * out_scale,
                                       acc[mt][nt][3] * out_scale);
        }
    }
}

// ============================================================================
// fp16x2 split kernels (pre-scaled so residual terms stay normal-range)
// ============================================================================
__global__ __launch_bounds__(256) void split_x(const float* __restrict__ src,
                                               __half* __restrict__ dst)
{   // 16384 x 512, scale 2^4
    const size_t i = (size_t)blockIdx.x * 256 + threadIdx.x;
    const size_t r = i >> 9, c = i & 511;
    const float v = src[i] * 16.0f;
    const __half h0 = __float2half_rn(v);
    const __half h1 = __float2half_rn(v - __half2float(h0));
    dst[r * 1024 + c] = h0;
    dst[r * 1024 + c + 512] = h1;
}
__global__ __launch_bounds__(256) void split_w1(const float* __restrict__ src,
                                                __half* __restrict__ dst)
{   // 2048 x 512, scale 2^6
    const size_t i = (size_t)blockIdx.x * 256 + threadIdx.x;
    const size_t r = i >> 9, c = i & 511;
    const float v = src[i] * 64.0f;
    const __half h0 = __float2half_rn(v);
    const __half h1 = __float2half_rn(v - __half2float(h0));
    dst[r * 1024 + c] = h0;
    dst[r * 1024 + c + 512] = h1;
}
__global__ __launch_bounds__(256) void split_w2(const float* __restrict__ src,
                                                __half* __restrict__ dst)
{   // 512 x 2048, scale 2^6
    const size_t i = (size_t)blockIdx.x * 256 + threadIdx.x;
    const size_t r = i >> 11, c = i & 2047;
    const float v = src[i] * 64.0f;
    const __half h0 = __float2half_rn(v);
    const __half h1 = __float2half_rn(v - __half2float(h0));
    dst[r * 4096 + c] = h0;
    dst[r * 4096 + c + 2048] = h1;
}

// ============================================================================
// Reset per-replay accumulators (graph-deterministic)
// ============================================================================
__global__ void reset_kernel()
{
    g_flag_count = 0;
    g_fix_delta = 0;
}

// ============================================================================
// LIF scan (t=4): provisional spikes from fp16x2 h; flag near-threshold
// ============================================================================
__global__ __launch_bounds__(256) void lif_kernel()
{
    const size_t idx = (size_t)blockIdx.x * 256 + threadIdx.x; // (b,s,hid)
    const int    hid = (int)(idx & 2047);
    const size_t bs  = idx >> 11;
    const size_t b   = bs >> 8;
    const size_t s   = bs & 255;
    const size_t bse = ((b * 4) * 256 + s) * 2048 + hid;
    const size_t ts  = 256UL * 2048UL;

    const float beta = (float)(1.0 - 1.0 / 20.0);
    const __half one  = __float2half(1.0f);
    const __half zero = __float2half(0.0f);
    float v = 0.0f;
    int cnt = 0;
    bool flagged = false;

    #pragma unroll
    for (int t = 0; t < 4; t++) {
        v = fmaf(beta, v, g_h[bse + (size_t)t * ts]);
        flagged |= (fabsf(v - 1.0f) < FLAG_EPS);
        const bool fire = (v > 1.0f);
        g_spk[bse + (size_t)t * ts] = fire ? one : zero;
        cnt += fire ? 1 : 0;
        v = fire ? 0.0f : v;
    }

    if (flagged) {
        const unsigned int pos = atomicAdd(&g_flag_count, 1u);
        if (pos < FLAG_CAP) g_flags[pos] = (unsigned int)idx;
    }

    #pragma unroll
    for (int o = 16; o; o >>= 1) cnt += __shfl_down_sync(0xFFFFFFFFu, cnt, o);
    __shared__ int warpsum[8];
    if ((threadIdx.x & 31) == 0) warpsum[threadIdx.x >> 5] = cnt;
    __syncthreads();
    if (threadIdx.x == 0) {
        int tot = 0;
        #pragma unroll
        for (int w = 0; w < 8; w++) tot += warpsum[w];
        g_partial[blockIdx.x] = (unsigned int)tot;
    }
}

// ============================================================================
// Sparse fp32 fixup: one thread per flagged neuron. Recomputes h in fp32 with
// sequential ascending-k fma (same arithmetic as the validated fp32 kernel),
// redoes the scan, patches spikes and the count delta.
// ============================================================================
__global__ __launch_bounds__(128) void fixup_kernel(
    const float* __restrict__ x, const float* __restrict__ w1)
{
    const unsigned int n = min(g_flag_count, FLAG_CAP);
    int delta = 0;

    for (unsigned int i = blockIdx.x * 128 + threadIdx.x; i < n;
         i += gridDim.x * 128) {
        const unsigned int idx = g_flags[i];
        const int    hid = (int)(idx & 2047u);
        const size_t bs  = idx >> 11;
        const size_t b   = bs >> 8;
        const size_t s   = bs & 255;
        const float* wrow = w1 + (size_t)hid * 512;
        const size_t bse  = ((b * 4) * 256 + s) * 2048 + hid;
        const size_t ts   = 256UL * 2048UL;

        const float beta = (float)(1.0 - 1.0 / 20.0);
        const __half one  = __float2half(1.0f);
        const __half zero = __float2half(0.0f);
        float v = 0.0f;

        #pragma unroll
        for (int t = 0; t < 4; t++) {
            const float* xrow = x + (((b * 4 + t) * 256 + s) << 9);
            float acc = 0.0f;
            #pragma unroll 8
            for (int k = 0; k < 512; k++) acc = fmaf(xrow[k], wrow[k], acc);
            v = fmaf(beta, v, acc);
            const bool fire = (v > 1.0f);
            const __half old = g_spk[bse + (size_t)t * ts];
            const bool oldf = (__half2float(old) > 0.5f);
            if (fire != oldf) {
                g_spk[bse + (size_t)t * ts] = fire ? one : zero;
                delta += fire ? 1 : -1;
            }
            v = fire ? 0.0f : v;
        }
    }

    // block-reduce delta, single atomic per block
    #pragma unroll
    for (int o = 16; o; o >>= 1) delta += __shfl_down_sync(0xFFFFFFFFu, delta, o);
    __shared__ int wsum[4];
    if ((threadIdx.x & 31) == 0) wsum[threadIdx.x >> 5] = delta;
    __syncthreads();
    if (threadIdx.x == 0) {
        int tot = wsum[0] + wsum[1] + wsum[2] + wsum[3];
        if (tot != 0) atomicAdd(&g_fix_delta, tot);
    }
}

__global__ __launch_bounds__(1024) void rate_kernel(float* __restrict__ out_rate)
{
    long long s = 0;
    for (int i = threadIdx.x; i < 32768; i += 1024) s += g_partial[i];
    #pragma unroll
    for (int o = 16; o; o >>= 1) s += __shfl_down_sync(0xFFFFFFFFu, s, o);
    __shared__ long long sh[32];
    if ((threadIdx.x & 31) == 0) sh[threadIdx.x >> 5] = s;
    __syncthreads();
    if (threadIdx.x == 0) {
        long long tot = 0;
        #pragma unroll
        for (int w = 0; w < 32; w++) tot += sh[w];
        tot += g_fix_delta;
        *out_rate = (float)((double)tot / 33554432.0);
    }
}

// ============================================================================
extern "C" void kernel_launch(void* const* d_in, const int* in_sizes, int n_in,
                              void* d_out, int out_size)
{
    const float* x  = (const float*)d_in[0];
    const float* w1 = (const float*)d_in[1];
    const float* w2 = (const float*)d_in[2];
    float* out = (float*)d_out;

    __half *xs, *w1s, *w2s, *spk;
    float* h;
    cudaGetSymbolAddress((void**)&xs,  g_xsplit);
    cudaGetSymbolAddress((void**)&w1s, g_w1split);
    cudaGetSymbolAddress((void**)&w2s, g_w2split);
    cudaGetSymbolAddress((void**)&spk, g_spk);
    cudaGetSymbolAddress((void**)&h,   g_h);

    cudaFuncSetAttribute(gemm_f16, cudaFuncAttributeMaxDynamicSharedMemorySize,
                         SMEM_ALLOC);

    reset_kernel<<<1, 1>>>();

    // splits
    split_x <<<32768, 256>>>(x,  xs);
    split_w1<<<4096,  256>>>(w1, w1s);
    split_w2<<<4096,  256>>>(w2, w2s);

    // GEMM1: h = x @ w1^T (fp16x2 x fp16x2 -> 4 products, K' = 2048)
    KMap m1 = {{0, 0, 1, 1}, {0, 1, 0, 1}};
    gemm_f16<<<dim3(2048 / BN, 16384 / BM), 256, SMEM_ALLOC>>>(
        xs, w1s, h, 2048, 2048 / BK, 1024, 1024, 9, 0.0009765625f, m1);

    // LIF (provisional + flagging), then sparse fp32 fixup, then rate
    lif_kernel<<<32768, 256>>>();
    fixup_kernel<<<1024, 128>>>(x, w1);
    rate_kernel<<<1, 1024>>>(out + (out_size - 1));

    // GEMM2: out = spk @ w2^T (spikes exact; w2 fp16x2 -> 2 products, K'=4096)
    KMap m2 = {{0, 0, 0, 0}, {0, 1, 0, 0}};
    gemm_f16<<<dim3(512 / BN, 16384 / BM), 256, SMEM_ALLOC>>>(
        spk, w2s, out, 512, 4096 / BK, 2048, 4096, 11, 0.015625f, m2);
}